// round 1
// baseline (speedup 1.0000x reference)
#include <cuda_runtime.h>
#include <math.h>

#define NB   4
#define SEQ  2048
#define HID  1024
#define FAC  256
#define NHD  16
#define DK   64
#define ROWS (NB*SEQ)   /* 8192 */
#define BH   (NB*NHD)   /* 64   */

#define BM 128
#define BN 64
#define BK 16

/* ---------------- scratch (device globals: allocation-guard safe) -------- */
__device__ float g_q [ROWS*HID];
__device__ float g_k [ROWS*HID];
__device__ float g_v [ROWS*HID];
__device__ float g_h [ROWS*FAC];
__device__ float g_cv[ROWS*HID];
__device__ float g_sc[268435456];  /* 64 * 2048 * 2048 floats = 1 GiB */

/* ---------------- shared micro-kernel: 8x4 per-thread tile --------------- */
__device__ __forceinline__ void compute_tile(
    float (&acc)[8][4],
    const float (&As)[BK][BM], const float (&Bs)[BK][BN],
    int tx, int ty)
{
#pragma unroll
    for (int kk = 0; kk < BK; kk++) {
        float4 a0 = *(const float4*)&As[kk][ty*8];
        float4 a1 = *(const float4*)&As[kk][ty*8+4];
        float4 b0 = *(const float4*)&Bs[kk][tx*4];
        float av[8] = {a0.x,a0.y,a0.z,a0.w,a1.x,a1.y,a1.z,a1.w};
        float bv[4] = {b0.x,b0.y,b0.z,b0.w};
#pragma unroll
        for (int i = 0; i < 8; i++)
#pragma unroll
            for (int j = 0; j < 4; j++)
                acc[i][j] += av[i]*bv[j];
    }
}

/* ---------------- generic NN linear: C = act(A[M,K] @ W[K,N] + bias) ----- */
__global__ void __launch_bounds__(256) linear_kernel(
    const float* __restrict__ A, const float* __restrict__ W,
    const float* __restrict__ bias, float* __restrict__ C,
    int M, int N, int K, int act)
{
    __shared__ __align__(16) float As[BK][BM];
    __shared__ __align__(16) float Bs[BK][BN];
    const int tid = threadIdx.x;
    const int tx = tid & 15, ty = tid >> 4;
    const int row0 = blockIdx.x * BM;
    const int col0 = blockIdx.y * BN;
    const int ar = tid >> 2, ak = (tid & 3) << 2;   /* A tile: 128 rows x 16 k */
    const int bk = tid >> 4, bc = (tid & 15) << 2;  /* W tile: 16 k x 64 cols  */

    float acc[8][4];
#pragma unroll
    for (int i = 0; i < 8; i++)
#pragma unroll
        for (int j = 0; j < 4; j++) acc[i][j] = 0.f;

    for (int k0 = 0; k0 < K; k0 += BK) {
        float4 a0 = *(const float4*)(A + (size_t)(row0+ar   )*K + k0 + ak);
        float4 a1 = *(const float4*)(A + (size_t)(row0+ar+64)*K + k0 + ak);
        float4 w0 = *(const float4*)(W + (size_t)(k0+bk)*N + col0 + bc);
        As[ak+0][ar]    = a0.x; As[ak+1][ar]    = a0.y;
        As[ak+2][ar]    = a0.z; As[ak+3][ar]    = a0.w;
        As[ak+0][ar+64] = a1.x; As[ak+1][ar+64] = a1.y;
        As[ak+2][ar+64] = a1.z; As[ak+3][ar+64] = a1.w;
        *(float4*)&Bs[bk][bc] = w0;
        __syncthreads();
        compute_tile(acc, As, Bs, tx, ty);
        __syncthreads();
    }

#pragma unroll
    for (int i = 0; i < 8; i++) {
        int r = row0 + ty*8 + i;
#pragma unroll
        for (int j = 0; j < 4; j++) {
            int c = col0 + tx*4 + j;
            float v = acc[i][j] + bias[c];
            if (act) v = (v > 0.f) ? v : 0.2f*v;
            C[(size_t)r*N + c] = v;
        }
    }
}

/* ---------------- batched QK^T: Sc[bh,i,j] = q_bh[i,:] . k_bh[j,:] -------- */
__global__ void __launch_bounds__(256) qk_kernel(
    const float* __restrict__ Q, const float* __restrict__ Km,
    float* __restrict__ Sc)
{
    __shared__ __align__(16) float As[BK][BM];
    __shared__ __align__(16) float Bs[BK][BN];
    const int bh = blockIdx.z;
    const int b = bh >> 4, h = bh & 15;
    const float* Aq = Q  + (size_t)b*SEQ*HID + h*DK;
    const float* Bk = Km + (size_t)b*SEQ*HID + h*DK;
    float* Cp = Sc + (size_t)bh*SEQ*SEQ;
    const int i0 = blockIdx.x * BM;
    const int j0 = blockIdx.y * BN;

    const int tid = threadIdx.x;
    const int tx = tid & 15, ty = tid >> 4;
    const int ar = tid >> 2, ak = (tid & 3) << 2;
    const int jr = tid >> 2, jk = (tid & 3) << 2;

    float acc[8][4];
#pragma unroll
    for (int i = 0; i < 8; i++)
#pragma unroll
        for (int j = 0; j < 4; j++) acc[i][j] = 0.f;

    for (int k0 = 0; k0 < DK; k0 += BK) {
        float4 a0 = *(const float4*)(Aq + (size_t)(i0+ar   )*HID + k0 + ak);
        float4 a1 = *(const float4*)(Aq + (size_t)(i0+ar+64)*HID + k0 + ak);
        float4 kb = *(const float4*)(Bk + (size_t)(j0+jr)*HID + k0 + jk);
        As[ak+0][ar]    = a0.x; As[ak+1][ar]    = a0.y;
        As[ak+2][ar]    = a0.z; As[ak+3][ar]    = a0.w;
        As[ak+0][ar+64] = a1.x; As[ak+1][ar+64] = a1.y;
        As[ak+2][ar+64] = a1.z; As[ak+3][ar+64] = a1.w;
        Bs[jk+0][jr] = kb.x; Bs[jk+1][jr] = kb.y;
        Bs[jk+2][jr] = kb.z; Bs[jk+3][jr] = kb.w;
        __syncthreads();
        compute_tile(acc, As, Bs, tx, ty);
        __syncthreads();
    }

#pragma unroll
    for (int i = 0; i < 8; i++) {
        size_t r = (size_t)(i0 + ty*8 + i)*SEQ + j0 + tx*4;
#pragma unroll
        for (int j = 0; j < 4; j++) Cp[r + j] = acc[i][j];
    }
}

/* ---------------- fused scale + mask + softmax over each score row ------- */
__global__ void __launch_bounds__(256) softmax_kernel(
    float* __restrict__ Sc, const int* __restrict__ mask)
{
    const int i  = blockIdx.x;
    const int bh = blockIdx.y;
    const int b  = bh >> 4;
    float* row = Sc + ((size_t)bh*SEQ + i)*SEQ;
    const int* mrow = mask + b*SEQ;
    const int tid = threadIdx.x;

    float loc[8];
    float m = -3.4e38f;
#pragma unroll
    for (int t = 0; t < 8; t++) {
        int j = tid + (t << 8);
        float v = row[j] * 0.125f;           /* 1/sqrt(64) */
        if (mrow[j] == 0) v = -1e20f;
        loc[t] = v;
        m = fmaxf(m, v);
    }

    __shared__ float red[8];
    __shared__ float bcv[2];
#pragma unroll
    for (int o = 16; o; o >>= 1) m = fmaxf(m, __shfl_xor_sync(0xffffffffu, m, o));
    if ((tid & 31) == 0) red[tid >> 5] = m;
    __syncthreads();
    if (tid == 0) {
        float mm = red[0];
        for (int w = 1; w < 8; w++) mm = fmaxf(mm, red[w]);
        bcv[0] = mm;
    }
    __syncthreads();
    m = bcv[0];

    float s = 0.f;
#pragma unroll
    for (int t = 0; t < 8; t++) {
        float e = __expf(loc[t] - m);
        loc[t] = e;
        s += e;
    }
#pragma unroll
    for (int o = 16; o; o >>= 1) s += __shfl_xor_sync(0xffffffffu, s, o);
    if ((tid & 31) == 0) red[tid >> 5] = s;
    __syncthreads();
    if (tid == 0) {
        float ss = 0.f;
        for (int w = 0; w < 8; w++) ss += red[w];
        bcv[1] = ss;
    }
    __syncthreads();
    float inv = 1.f / bcv[1];
#pragma unroll
    for (int t = 0; t < 8; t++) row[tid + (t << 8)] = loc[t] * inv;
}

/* ---------------- batched PV: cv_bh = attn_bh[S,S] @ v_bh[S,64] ----------- */
__global__ void __launch_bounds__(256) pv_kernel(
    const float* __restrict__ Sc, const float* __restrict__ V,
    float* __restrict__ Cv)
{
    __shared__ __align__(16) float As[BK][BM];
    __shared__ __align__(16) float Bs[BK][BN];
    const int bh = blockIdx.z;
    const int b = bh >> 4, h = bh & 15;
    const float* Ap = Sc + (size_t)bh*SEQ*SEQ;          /* lda = SEQ */
    const float* Bv = V  + (size_t)b*SEQ*HID + h*DK;    /* ldb = HID */
    float* Cp = Cv + (size_t)b*SEQ*HID + h*DK;          /* ldc = HID */
    const int i0 = blockIdx.x * BM;

    const int tid = threadIdx.x;
    const int tx = tid & 15, ty = tid >> 4;
    const int ar = tid >> 2, ak = (tid & 3) << 2;
    const int bk = tid >> 4, bc = (tid & 15) << 2;

    float acc[8][4];
#pragma unroll
    for (int i = 0; i < 8; i++)
#pragma unroll
        for (int j = 0; j < 4; j++) acc[i][j] = 0.f;

    for (int k0 = 0; k0 < SEQ; k0 += BK) {
        float4 a0 = *(const float4*)(Ap + (size_t)(i0+ar   )*SEQ + k0 + ak);
        float4 a1 = *(const float4*)(Ap + (size_t)(i0+ar+64)*SEQ + k0 + ak);
        float4 v0 = *(const float4*)(Bv + (size_t)(k0+bk)*HID + bc);
        As[ak+0][ar]    = a0.x; As[ak+1][ar]    = a0.y;
        As[ak+2][ar]    = a0.z; As[ak+3][ar]    = a0.w;
        As[ak+0][ar+64] = a1.x; As[ak+1][ar+64] = a1.y;
        As[ak+2][ar+64] = a1.z; As[ak+3][ar+64] = a1.w;
        *(float4*)&Bs[bk][bc] = v0;
        __syncthreads();
        compute_tile(acc, As, Bs, tx, ty);
        __syncthreads();
    }

#pragma unroll
    for (int i = 0; i < 8; i++) {
        size_t r = (size_t)(i0 + ty*8 + i)*HID + tx*4;
#pragma unroll
        for (int j = 0; j < 4; j++) Cp[r + j] = acc[i][j];
    }
}

/* ---------------- host orchestration ------------------------------------- */
extern "C" void kernel_launch(void* const* d_in, const int* in_sizes, int n_in,
                              void* d_out, int out_size)
{
    const float* query = (const float*)d_in[0];
    const float* key   = (const float*)d_in[1];
    const float* value = (const float*)d_in[2];
    const int*   mask  = (const int*)  d_in[3];
    const float* Wpq = (const float*)d_in[4],  *bpq = (const float*)d_in[5];
    const float* Wtq = (const float*)d_in[6],  *btq = (const float*)d_in[7];
    const float* Wpk = (const float*)d_in[8],  *bpk = (const float*)d_in[9];
    const float* Wtk = (const float*)d_in[10], *btk = (const float*)d_in[11];
    const float* Wpv = (const float*)d_in[12], *bpv = (const float*)d_in[13];
    const float* Wtv = (const float*)d_in[14], *btv = (const float*)d_in[15];
    const float* Wpo = (const float*)d_in[16], *bpo = (const float*)d_in[17];
    const float* Wto = (const float*)d_in[18], *bto = (const float*)d_in[19];
    float* out = (float*)d_out;

    float *q_, *k_, *v_, *h_, *cv_, *sc_;
    cudaGetSymbolAddress((void**)&q_,  g_q);
    cudaGetSymbolAddress((void**)&k_,  g_k);
    cudaGetSymbolAddress((void**)&v_,  g_v);
    cudaGetSymbolAddress((void**)&h_,  g_h);
    cudaGetSymbolAddress((void**)&cv_, g_cv);
    cudaGetSymbolAddress((void**)&sc_, g_sc);

    dim3 blk(256);
    dim3 gproj(ROWS/BM, FAC/BN);   /* (64, 4)  */
    dim3 gtran(ROWS/BM, HID/BN);   /* (64, 16) */

    /* q/k/v factored linears */
    linear_kernel<<<gproj, blk>>>(query, Wpq, bpq, h_, ROWS, FAC, HID, 1);
    linear_kernel<<<gtran, blk>>>(h_,    Wtq, btq, q_, ROWS, HID, FAC, 0);
    linear_kernel<<<gproj, blk>>>(key,   Wpk, bpk, h_, ROWS, FAC, HID, 1);
    linear_kernel<<<gtran, blk>>>(h_,    Wtk, btk, k_, ROWS, HID, FAC, 0);
    linear_kernel<<<gproj, blk>>>(value, Wpv, bpv, h_, ROWS, FAC, HID, 1);
    linear_kernel<<<gtran, blk>>>(h_,    Wtv, btv, v_, ROWS, HID, FAC, 0);

    /* attention */
    qk_kernel<<<dim3(SEQ/BM, SEQ/BN, BH), blk>>>(q_, k_, sc_);
    softmax_kernel<<<dim3(SEQ, BH), blk>>>(sc_, mask);
    pv_kernel<<<dim3(SEQ/BM, 1, BH), blk>>>(sc_, v_, cv_);

    /* output factored linear */
    linear_kernel<<<gproj, blk>>>(cv_, Wpo, bpo, h_,  ROWS, FAC, HID, 1);
    linear_kernel<<<gtran, blk>>>(h_,  Wto, bto, out, ROWS, HID, FAC, 0);
}

// round 2
// speedup vs baseline: 2.1889x; 2.1889x over previous
#include <cuda_runtime.h>
#include <math.h>
#include <stdint.h>

#define NB   4
#define SEQ  2048
#define HID  1024
#define FAC  256
#define NHD  16
#define DK   64
#define ROWS (NB*SEQ)   /* 8192 */
#define BH   (NB*NHD)   /* 64   */

#define BM 128
#define BN 64
#define BK 32
#define LDA 36   /* BK+4, A stored [BM][LDA] (m-major) */
#define LDB 68   /* BN+4, B stored [BK][LDB] (k-major) */
#define LDBT 36  /* BK+4, B stored [BN][LDBT] (n-major, for K-matrix) */

/* ---------------- scratch ------------------------------------------------ */
__device__ float g_q  [ROWS*HID];
__device__ float g_k  [ROWS*HID];
__device__ float g_v  [ROWS*HID];
__device__ float g_h  [ROWS*FAC];
__device__ float g_cv [ROWS*HID];
__device__ float g_m  [BH*SEQ];
__device__ float g_inv[BH*SEQ];
__device__ float g_sc [268435456];  /* 64*2048*2048 floats */

/* ---------------- helpers ------------------------------------------------ */
__device__ __forceinline__ float tf32r(float x) {
    uint32_t u;
    asm("cvt.rna.tf32.f32 %0, %1;" : "=r"(u) : "f"(x));
    return __uint_as_float(u);
}
__device__ __forceinline__ void mma_tf32(float c[4], const uint32_t a[4], const uint32_t b[2]) {
    asm volatile(
        "mma.sync.aligned.m16n8k8.row.col.f32.tf32.tf32.f32 "
        "{%0,%1,%2,%3}, {%4,%5,%6,%7}, {%8,%9}, {%0,%1,%2,%3};"
        : "+f"(c[0]), "+f"(c[1]), "+f"(c[2]), "+f"(c[3])
        : "r"(a[0]), "r"(a[1]), "r"(a[2]), "r"(a[3]), "r"(b[0]), "r"(b[1]));
}
__device__ __forceinline__ float4 cvt4(float4 v) {
    v.x = tf32r(v.x); v.y = tf32r(v.y); v.z = tf32r(v.z); v.w = tf32r(v.w);
    return v;
}

/* =================== TF32 linear: C = act(A[M,K]@W[K,N]+b) =============== */
__global__ void __launch_bounds__(256) linear_tc(
    const float* __restrict__ A, const float* __restrict__ W,
    const float* __restrict__ bias, float* __restrict__ C,
    int M, int N, int K, int act)
{
    __shared__ __align__(16) float As[BM][LDA];
    __shared__ __align__(16) float Bs[BK][LDB];

    const int tid = threadIdx.x;
    const int row0 = blockIdx.x * BM;
    const int col0 = blockIdx.y * BN;

    const int arow = tid >> 3, acol = (tid & 7) << 2;   /* 32 rows x 32 k per pass */
    const int wk   = tid >> 4, wn   = (tid & 15) << 2;  /* 16 k x 64 n per pass   */

    const int wid = tid >> 5, lane = tid & 31;
    const int wm = (wid >> 1) * 32, wncol = (wid & 1) * 32;
    const int r = lane >> 2, cq = lane & 3;

    float acc[2][4][4];
#pragma unroll
    for (int mt = 0; mt < 2; mt++)
#pragma unroll
        for (int nt = 0; nt < 4; nt++)
#pragma unroll
            for (int i = 0; i < 4; i++) acc[mt][nt][i] = 0.f;

    float4 pa[4], pb[2];
    const int nch = K / BK;

    /* prefetch chunk 0 */
#pragma unroll
    for (int p = 0; p < 4; p++)
        pa[p] = *(const float4*)(A + (size_t)(row0 + arow + 32*p)*K + acol);
#pragma unroll
    for (int p = 0; p < 2; p++)
        pb[p] = *(const float4*)(W + (size_t)(wk + 16*p)*N + col0 + wn);

    for (int c = 0; c < nch; c++) {
#pragma unroll
        for (int p = 0; p < 4; p++)
            *(float4*)&As[arow + 32*p][acol] = cvt4(pa[p]);
#pragma unroll
        for (int p = 0; p < 2; p++)
            *(float4*)&Bs[wk + 16*p][wn] = cvt4(pb[p]);
        __syncthreads();

        if (c + 1 < nch) {
            int k0 = (c + 1) * BK;
#pragma unroll
            for (int p = 0; p < 4; p++)
                pa[p] = *(const float4*)(A + (size_t)(row0 + arow + 32*p)*K + k0 + acol);
#pragma unroll
            for (int p = 0; p < 2; p++)
                pb[p] = *(const float4*)(W + (size_t)(k0 + wk + 16*p)*N + col0 + wn);
        }

#pragma unroll
        for (int kk = 0; kk < BK; kk += 8) {
            uint32_t af[2][4];
#pragma unroll
            for (int mt = 0; mt < 2; mt++) {
                int m = wm + mt*16;
                af[mt][0] = __float_as_uint(As[m + r    ][kk + cq    ]);
                af[mt][1] = __float_as_uint(As[m + r + 8][kk + cq    ]);
                af[mt][2] = __float_as_uint(As[m + r    ][kk + cq + 4]);
                af[mt][3] = __float_as_uint(As[m + r + 8][kk + cq + 4]);
            }
            uint32_t bf[4][2];
#pragma unroll
            for (int nt = 0; nt < 4; nt++) {
                int n = wncol + nt*8 + r;
                bf[nt][0] = __float_as_uint(Bs[kk + cq    ][n]);
                bf[nt][1] = __float_as_uint(Bs[kk + cq + 4][n]);
            }
#pragma unroll
            for (int mt = 0; mt < 2; mt++)
#pragma unroll
                for (int nt = 0; nt < 4; nt++)
                    mma_tf32(acc[mt][nt], af[mt], bf[nt]);
        }
        __syncthreads();
    }

#pragma unroll
    for (int mt = 0; mt < 2; mt++)
#pragma unroll
        for (int nt = 0; nt < 4; nt++) {
            int col = col0 + wncol + nt*8 + cq*2;
            float b0 = bias[col], b1 = bias[col + 1];
#pragma unroll
            for (int hrow = 0; hrow < 2; hrow++) {
                int row = row0 + wm + mt*16 + r + hrow*8;
                float v0 = acc[mt][nt][hrow*2 + 0] + b0;
                float v1 = acc[mt][nt][hrow*2 + 1] + b1;
                if (act) {
                    v0 = (v0 > 0.f) ? v0 : 0.2f*v0;
                    v1 = (v1 > 0.f) ? v1 : 0.2f*v1;
                }
                float2 o = make_float2(v0, v1);
                *(float2*)&C[(size_t)row*N + col] = o;
            }
        }
}

/* =================== TF32 QK^T (scaled) ================================== */
__global__ void __launch_bounds__(256) qk_tc(
    const float* __restrict__ Q, const float* __restrict__ Km,
    float* __restrict__ Sc)
{
    __shared__ __align__(16) float As[BM][LDA];
    __shared__ __align__(16) float Ks[BN][LDBT];

    const int bh = blockIdx.z;
    const int b = bh >> 4, h = bh & 15;
    const float* Aq = Q  + (size_t)b*SEQ*HID + h*DK;
    const float* Bk = Km + (size_t)b*SEQ*HID + h*DK;
    float* Cp = Sc + (size_t)bh*SEQ*SEQ;
    const int i0 = blockIdx.x * BM;
    const int j0 = blockIdx.y * BN;

    const int tid = threadIdx.x;
    const int arow = tid >> 3, acol = (tid & 7) << 2;
    const int krow = tid >> 3, kcol = (tid & 7) << 2;

    const int wid = tid >> 5, lane = tid & 31;
    const int wm = (wid >> 1) * 32, wncol = (wid & 1) * 32;
    const int r = lane >> 2, cq = lane & 3;

    float acc[2][4][4];
#pragma unroll
    for (int mt = 0; mt < 2; mt++)
#pragma unroll
        for (int nt = 0; nt < 4; nt++)
#pragma unroll
            for (int i = 0; i < 4; i++) acc[mt][nt][i] = 0.f;

    float4 pa[4], pk[2];
#pragma unroll
    for (int p = 0; p < 4; p++)
        pa[p] = *(const float4*)(Aq + (size_t)(i0 + arow + 32*p)*HID + acol);
#pragma unroll
    for (int p = 0; p < 2; p++)
        pk[p] = *(const float4*)(Bk + (size_t)(j0 + krow + 32*p)*HID + kcol);

    for (int c = 0; c < DK/BK; c++) {
#pragma unroll
        for (int p = 0; p < 4; p++)
            *(float4*)&As[arow + 32*p][acol] = cvt4(pa[p]);
#pragma unroll
        for (int p = 0; p < 2; p++)
            *(float4*)&Ks[krow + 32*p][kcol] = cvt4(pk[p]);
        __syncthreads();

        if (c + 1 < DK/BK) {
            int k0 = (c + 1) * BK;
#pragma unroll
            for (int p = 0; p < 4; p++)
                pa[p] = *(const float4*)(Aq + (size_t)(i0 + arow + 32*p)*HID + k0 + acol);
#pragma unroll
            for (int p = 0; p < 2; p++)
                pk[p] = *(const float4*)(Bk + (size_t)(j0 + krow + 32*p)*HID + k0 + kcol);
        }

#pragma unroll
        for (int kk = 0; kk < BK; kk += 8) {
            uint32_t af[2][4];
#pragma unroll
            for (int mt = 0; mt < 2; mt++) {
                int m = wm + mt*16;
                af[mt][0] = __float_as_uint(As[m + r    ][kk + cq    ]);
                af[mt][1] = __float_as_uint(As[m + r + 8][kk + cq    ]);
                af[mt][2] = __float_as_uint(As[m + r    ][kk + cq + 4]);
                af[mt][3] = __float_as_uint(As[m + r + 8][kk + cq + 4]);
            }
            uint32_t bf[4][2];
#pragma unroll
            for (int nt = 0; nt < 4; nt++) {
                int n = wncol + nt*8 + r;
                bf[nt][0] = __float_as_uint(Ks[n][kk + cq    ]);
                bf[nt][1] = __float_as_uint(Ks[n][kk + cq + 4]);
            }
#pragma unroll
            for (int mt = 0; mt < 2; mt++)
#pragma unroll
                for (int nt = 0; nt < 4; nt++)
                    mma_tf32(acc[mt][nt], af[mt], bf[nt]);
        }
        __syncthreads();
    }

#pragma unroll
    for (int mt = 0; mt < 2; mt++)
#pragma unroll
        for (int nt = 0; nt < 4; nt++) {
            int col = j0 + wncol + nt*8 + cq*2;
#pragma unroll
            for (int hrow = 0; hrow < 2; hrow++) {
                int row = i0 + wm + mt*16 + r + hrow*8;
                float2 o = make_float2(acc[mt][nt][hrow*2+0] * 0.125f,
                                       acc[mt][nt][hrow*2+1] * 0.125f);
                *(float2*)&Cp[(size_t)row*SEQ + col] = o;
            }
        }
}

/* =========== per-row softmax stats: max + 1/sum (mask folded) ============ */
__global__ void __launch_bounds__(256) stats_kernel(
    const float* __restrict__ Sc, const int* __restrict__ mask,
    float* __restrict__ gm, float* __restrict__ ginv)
{
    const int i  = blockIdx.x;
    const int bh = blockIdx.y;
    const int b  = bh >> 4;
    const float* row = Sc + ((size_t)bh*SEQ + i)*SEQ;
    const int* mrow = mask + b*SEQ;
    const int tid = threadIdx.x;

    float loc[8];
    float m = -3.4e38f;
#pragma unroll
    for (int t = 0; t < 8; t++) {
        int j = tid + (t << 8);
        float v = row[j];
        if (mrow[j] == 0) v = -1e20f;
        loc[t] = v;
        m = fmaxf(m, v);
    }

    __shared__ float red[8];
    __shared__ float bcv[2];
#pragma unroll
    for (int o = 16; o; o >>= 1) m = fmaxf(m, __shfl_xor_sync(0xffffffffu, m, o));
    if ((tid & 31) == 0) red[tid >> 5] = m;
    __syncthreads();
    if (tid == 0) {
        float mm = red[0];
        for (int w = 1; w < 8; w++) mm = fmaxf(mm, red[w]);
        bcv[0] = mm;
    }
    __syncthreads();
    m = bcv[0];

    float s = 0.f;
#pragma unroll
    for (int t = 0; t < 8; t++) s += __expf(loc[t] - m);
#pragma unroll
    for (int o = 16; o; o >>= 1) s += __shfl_xor_sync(0xffffffffu, s, o);
    if ((tid & 31) == 0) red[tid >> 5] = s;
    __syncthreads();
    if (tid == 0) {
        float ss = 0.f;
        for (int w = 0; w < 8; w++) ss += red[w];
        bcv[1] = ss;
    }
    __syncthreads();
    if (tid == 0) {
        gm  [(size_t)bh*SEQ + i] = m;
        ginv[(size_t)bh*SEQ + i] = 1.f / bcv[1];
    }
}

/* =================== TF32 PV with fused exp/normalize ==================== */
__global__ void __launch_bounds__(256) pv_tc(
    const float* __restrict__ Sc, const float* __restrict__ V,
    const int* __restrict__ mask,
    const float* __restrict__ gm, const float* __restrict__ ginv,
    float* __restrict__ Cv)
{
    __shared__ __align__(16) float As[BM][LDA];
    __shared__ __align__(16) float Bs[BK][LDB];
    __shared__ float sm_m[BM], sm_v[BM];

    const int bh = blockIdx.z;
    const int b = bh >> 4, h = bh & 15;
    const float* Ap = Sc + (size_t)bh*SEQ*SEQ;
    const float* Bv = V  + (size_t)b*SEQ*HID + h*DK;
    const int* mrow = mask + b*SEQ;
    float* Cp = Cv + (size_t)b*SEQ*HID + h*DK;
    const int i0 = blockIdx.x * BM;

    const int tid = threadIdx.x;
    const int arow = tid >> 3, acol = (tid & 7) << 2;
    const int vk   = tid >> 4, vn   = (tid & 15) << 2;

    const int wid = tid >> 5, lane = tid & 31;
    const int wm = (wid >> 1) * 32, wncol = (wid & 1) * 32;
    const int r = lane >> 2, cq = lane & 3;

    if (tid < BM) {
        sm_m[tid] = gm  [(size_t)bh*SEQ + i0 + tid];
        sm_v[tid] = ginv[(size_t)bh*SEQ + i0 + tid];
    }
    __syncthreads();

    float acc[2][4][4];
#pragma unroll
    for (int mt = 0; mt < 2; mt++)
#pragma unroll
        for (int nt = 0; nt < 4; nt++)
#pragma unroll
            for (int i = 0; i < 4; i++) acc[mt][nt][i] = 0.f;

    float4 pa[4]; float4 pb[2]; int4 pm;
    /* prefetch chunk 0 */
    pm = *(const int4*)(mrow + acol);
#pragma unroll
    for (int p = 0; p < 4; p++)
        pa[p] = *(const float4*)(Ap + (size_t)(i0 + arow + 32*p)*SEQ + acol);
#pragma unroll
    for (int p = 0; p < 2; p++)
        pb[p] = *(const float4*)(Bv + (size_t)(vk + 16*p)*HID + vn);

    const int nch = SEQ / BK;  /* 64 */
    for (int c = 0; c < nch; c++) {
#pragma unroll
        for (int p = 0; p < 4; p++) {
            float mi = sm_m[arow + 32*p];
            float4 s = pa[p];
            float4 pf;
            pf.x = pm.x ? __expf(s.x - mi) : 0.f;
            pf.y = pm.y ? __expf(s.y - mi) : 0.f;
            pf.z = pm.z ? __expf(s.z - mi) : 0.f;
            pf.w = pm.w ? __expf(s.w - mi) : 0.f;
            *(float4*)&As[arow + 32*p][acol] = cvt4(pf);
        }
#pragma unroll
        for (int p = 0; p < 2; p++)
            *(float4*)&Bs[vk + 16*p][vn] = cvt4(pb[p]);
        __syncthreads();

        if (c + 1 < nch) {
            int k0 = (c + 1) * BK;
            pm = *(const int4*)(mrow + k0 + acol);
#pragma unroll
            for (int p = 0; p < 4; p++)
                pa[p] = *(const float4*)(Ap + (size_t)(i0 + arow + 32*p)*SEQ + k0 + acol);
#pragma unroll
            for (int p = 0; p < 2; p++)
                pb[p] = *(const float4*)(Bv + (size_t)(k0 + vk + 16*p)*HID + vn);
        }

#pragma unroll
        for (int kk = 0; kk < BK; kk += 8) {
            uint32_t af[2][4];
#pragma unroll
            for (int mt = 0; mt < 2; mt++) {
                int m = wm + mt*16;
                af[mt][0] = __float_as_uint(As[m + r    ][kk + cq    ]);
                af[mt][1] = __float_as_uint(As[m + r + 8][kk + cq    ]);
                af[mt][2] = __float_as_uint(As[m + r    ][kk + cq + 4]);
                af[mt][3] = __float_as_uint(As[m + r + 8][kk + cq + 4]);
            }
            uint32_t bf[4][2];
#pragma unroll
            for (int nt = 0; nt < 4; nt++) {
                int n = wncol + nt*8 + r;
                bf[nt][0] = __float_as_uint(Bs[kk + cq    ][n]);
                bf[nt][1] = __float_as_uint(Bs[kk + cq + 4][n]);
            }
#pragma unroll
            for (int mt = 0; mt < 2; mt++)
#pragma unroll
                for (int nt = 0; nt < 4; nt++)
                    mma_tf32(acc[mt][nt], af[mt], bf[nt]);
        }
        __syncthreads();
    }

#pragma unroll
    for (int mt = 0; mt < 2; mt++)
#pragma unroll
        for (int nt = 0; nt < 4; nt++) {
            int col = wncol + nt*8 + cq*2;
#pragma unroll
            for (int hrow = 0; hrow < 2; hrow++) {
                int lrow = wm + mt*16 + r + hrow*8;
                float inv = sm_v[lrow];
                int row = i0 + lrow;
                float2 o = make_float2(acc[mt][nt][hrow*2+0] * inv,
                                       acc[mt][nt][hrow*2+1] * inv);
                *(float2*)&Cp[(size_t)row*HID + col] = o;
            }
        }
}

/* ---------------- host orchestration ------------------------------------- */
extern "C" void kernel_launch(void* const* d_in, const int* in_sizes, int n_in,
                              void* d_out, int out_size)
{
    const float* query = (const float*)d_in[0];
    const float* key   = (const float*)d_in[1];
    const float* value = (const float*)d_in[2];
    const int*   mask  = (const int*)  d_in[3];
    const float* Wpq = (const float*)d_in[4],  *bpq = (const float*)d_in[5];
    const float* Wtq = (const float*)d_in[6],  *btq = (const float*)d_in[7];
    const float* Wpk = (const float*)d_in[8],  *bpk = (const float*)d_in[9];
    const float* Wtk = (const float*)d_in[10], *btk = (const float*)d_in[11];
    const float* Wpv = (const float*)d_in[12], *bpv = (const float*)d_in[13];
    const float* Wtv = (const float*)d_in[14], *btv = (const float*)d_in[15];
    const float* Wpo = (const float*)d_in[16], *bpo = (const float*)d_in[17];
    const float* Wto = (const float*)d_in[18], *bto = (const float*)d_in[19];
    float* out = (float*)d_out;

    float *q_, *k_, *v_, *h_, *cv_, *sc_, *m_, *inv_;
    cudaGetSymbolAddress((void**)&q_,   g_q);
    cudaGetSymbolAddress((void**)&k_,   g_k);
    cudaGetSymbolAddress((void**)&v_,   g_v);
    cudaGetSymbolAddress((void**)&h_,   g_h);
    cudaGetSymbolAddress((void**)&cv_,  g_cv);
    cudaGetSymbolAddress((void**)&sc_,  g_sc);
    cudaGetSymbolAddress((void**)&m_,   g_m);
    cudaGetSymbolAddress((void**)&inv_, g_inv);

    dim3 blk(256);
    dim3 gproj(ROWS/BM, FAC/BN);   /* (64, 4)  */
    dim3 gtran(ROWS/BM, HID/BN);   /* (64, 16) */

    linear_tc<<<gproj, blk>>>(query, Wpq, bpq, h_, ROWS, FAC, HID, 1);
    linear_tc<<<gtran, blk>>>(h_,    Wtq, btq, q_, ROWS, HID, FAC, 0);
    linear_tc<<<gproj, blk>>>(key,   Wpk, bpk, h_, ROWS, FAC, HID, 1);
    linear_tc<<<gtran, blk>>>(h_,    Wtk, btk, k_, ROWS, HID, FAC, 0);
    linear_tc<<<gproj, blk>>>(value, Wpv, bpv, h_, ROWS, FAC, HID, 1);
    linear_tc<<<gtran, blk>>>(h_,    Wtv, btv, v_, ROWS, HID, FAC, 0);

    qk_tc<<<dim3(SEQ/BM, SEQ/BN, BH), blk>>>(q_, k_, sc_);
    stats_kernel<<<dim3(SEQ, BH), blk>>>(sc_, mask, m_, inv_);
    pv_tc<<<dim3(SEQ/BM, 1, BH), blk>>>(sc_, v_, mask, m_, inv_, cv_);

    linear_tc<<<gproj, blk>>>(cv_, Wpo, bpo, h_,  ROWS, FAC, HID, 1);
    linear_tc<<<gtran, blk>>>(h_,  Wto, bto, out, ROWS, HID, FAC, 0);
}

// round 3
// speedup vs baseline: 2.3516x; 1.0744x over previous
#include <cuda_runtime.h>
#include <math.h>
#include <stdint.h>

#define NB   4
#define SEQ  2048
#define HID  1024
#define FAC  256
#define NHD  16
#define DK   64
#define ROWS (NB*SEQ)   /* 8192 */
#define BH   (NB*NHD)   /* 64   */

#define BM 128
#define BN 64
#define BK 32
#define LDA  36   /* A smem: [BM][LDA], m-major  */
#define LDBN 36   /* B smem: [BN][LDBN], n-major */

/* ---------------- scratch ------------------------------------------------ */
__device__ float g_q  [ROWS*HID];
__device__ float g_k  [ROWS*HID];
__device__ float g_v  [ROWS*HID];
__device__ float g_h  [ROWS*FAC];
__device__ float g_cv [ROWS*HID];
__device__ float g_m  [BH*SEQ];
__device__ float g_inv[BH*SEQ];
__device__ float g_sc [268435456];  /* 64*2048*2048 floats */

/* ---------------- helpers ------------------------------------------------ */
__device__ __forceinline__ float tf32r(float x) {
    uint32_t u;
    asm("cvt.rna.tf32.f32 %0, %1;" : "=r"(u) : "f"(x));
    return __uint_as_float(u);
}
__device__ __forceinline__ float4 cvt4(float4 v) {
    v.x = tf32r(v.x); v.y = tf32r(v.y); v.z = tf32r(v.z); v.w = tf32r(v.w);
    return v;
}
__device__ __forceinline__ void mma_tf32(float c[4], const uint32_t a[4], const uint32_t b[2]) {
    asm volatile(
        "mma.sync.aligned.m16n8k8.row.col.f32.tf32.tf32.f32 "
        "{%0,%1,%2,%3}, {%4,%5,%6,%7}, {%8,%9}, {%0,%1,%2,%3};"
        : "+f"(c[0]), "+f"(c[1]), "+f"(c[2]), "+f"(c[3])
        : "r"(a[0]), "r"(a[1]), "r"(a[2]), "r"(a[3]), "r"(b[0]), "r"(b[1]));
}
__device__ __forceinline__ void ldsm4(uint32_t f[4], uint32_t addr) {
    asm volatile("ldmatrix.sync.aligned.m8n8.x4.shared.b16 {%0,%1,%2,%3}, [%4];"
        : "=r"(f[0]), "=r"(f[1]), "=r"(f[2]), "=r"(f[3]) : "r"(addr));
}
__device__ __forceinline__ uint32_t smem_u32(const void* p) {
    return (uint32_t)__cvta_generic_to_shared(p);
}

/* Fragment base addresses (bytes into smem) for ldmatrix.
   A tile (m-major [BM][LDA]):  matrices a0/a1/a2/a3 = (+0/+8 row, +0/+4 col)
   B tile (n-major [BN][LDBN]): matrices b0(nt),b1(nt),b0(nt+1),b1(nt+1)      */
__device__ __forceinline__ uint32_t a_frag_base(uint32_t smA, int wm, int mt, int lane) {
    int lr = lane & 7, sel = lane >> 3;
    int row = wm + mt*16 + lr + ((sel & 1) << 3);
    int col = (sel & 2) << 1;           /* 0 or 4 */
    return smA + (uint32_t)(row*LDA + col)*4u;
}
__device__ __forceinline__ uint32_t b_frag_base(uint32_t smB, int wn, int g, int lane) {
    int lr = lane & 7, sel = lane >> 3;
    int row = wn + g*16 + lr + ((sel & 2) << 2);  /* +8 rows selects 2nd ntile */
    int col = (sel & 1) << 2;                      /* +4 k selects b1 */
    return smB + (uint32_t)(row*LDBN + col)*4u;
}

/* Shared compute core: 4 kk-blocks of 8, per-warp 32x32 tile */
#define MMA_CHUNK(aB0, aB1, bB0, bB1, acc)                                    \
    _Pragma("unroll")                                                         \
    for (int kk = 0; kk < BK; kk += 8) {                                      \
        uint32_t af0[4], af1[4], bq0[4], bq1[4];                              \
        ldsm4(af0, (aB0) + kk*4);                                             \
        ldsm4(af1, (aB1) + kk*4);                                             \
        ldsm4(bq0, (bB0) + kk*4);                                             \
        ldsm4(bq1, (bB1) + kk*4);                                             \
        mma_tf32(acc[0][0], af0, &bq0[0]);                                    \
        mma_tf32(acc[0][1], af0, &bq0[2]);                                    \
        mma_tf32(acc[0][2], af0, &bq1[0]);                                    \
        mma_tf32(acc[0][3], af0, &bq1[2]);                                    \
        mma_tf32(acc[1][0], af1, &bq0[0]);                                    \
        mma_tf32(acc[1][1], af1, &bq0[2]);                                    \
        mma_tf32(acc[1][2], af1, &bq1[0]);                                    \
        mma_tf32(acc[1][3], af1, &bq1[2]);                                    \
    }

/* =================== TF32 linear: C = act(A[M,K]@W[K,N]+b) =============== */
__global__ void __launch_bounds__(256) linear_tc(
    const float* __restrict__ A, const float* __restrict__ W,
    const float* __restrict__ bias, float* __restrict__ C,
    int M, int N, int K, int act)
{
    __shared__ __align__(16) float As[BM][LDA];
    __shared__ __align__(16) float Bs[BN][LDBN];

    const int tid = threadIdx.x;
    const int row0 = blockIdx.x * BM;
    const int col0 = blockIdx.y * BN;

    /* A writer: 4 passes of 32 rows x 32 k, float4 along k */
    const int arow = tid >> 3, acol = (tid & 7) << 2;
    /* B writer: n-major; 64 n x 4 k-groups, 2 passes of k+16 */
    const int bn = tid & 63, bk4 = (tid >> 6) << 2;

    const int wid = tid >> 5, lane = tid & 31;
    const int wm = (wid >> 1) * 32, wn = (wid & 1) * 32;
    const int r = lane >> 2, cq = lane & 3;

    const uint32_t smA = smem_u32(&As[0][0]);
    const uint32_t smB = smem_u32(&Bs[0][0]);
    const uint32_t aB0 = a_frag_base(smA, wm, 0, lane);
    const uint32_t aB1 = a_frag_base(smA, wm, 1, lane);
    const uint32_t bB0 = b_frag_base(smB, wn, 0, lane);
    const uint32_t bB1 = b_frag_base(smB, wn, 1, lane);

    float acc[2][4][4];
#pragma unroll
    for (int mt = 0; mt < 2; mt++)
#pragma unroll
        for (int nt = 0; nt < 4; nt++)
#pragma unroll
            for (int i = 0; i < 4; i++) acc[mt][nt][i] = 0.f;

    float4 pa[4];
    float  pb[2][4];
    const int nch = K / BK;

#pragma unroll
    for (int p = 0; p < 4; p++)
        pa[p] = *(const float4*)(A + (size_t)(row0 + arow + 32*p)*K + acol);
#pragma unroll
    for (int p = 0; p < 2; p++)
#pragma unroll
        for (int j = 0; j < 4; j++)
            pb[p][j] = W[(size_t)(bk4 + 16*p + j)*N + col0 + bn];

    for (int c = 0; c < nch; c++) {
#pragma unroll
        for (int p = 0; p < 4; p++)
            *(float4*)&As[arow + 32*p][acol] = cvt4(pa[p]);
#pragma unroll
        for (int p = 0; p < 2; p++) {
            float4 t = make_float4(pb[p][0], pb[p][1], pb[p][2], pb[p][3]);
            *(float4*)&Bs[bn][bk4 + 16*p] = cvt4(t);
        }
        __syncthreads();

        if (c + 1 < nch) {
            int k0 = (c + 1) * BK;
#pragma unroll
            for (int p = 0; p < 4; p++)
                pa[p] = *(const float4*)(A + (size_t)(row0 + arow + 32*p)*K + k0 + acol);
#pragma unroll
            for (int p = 0; p < 2; p++)
#pragma unroll
                for (int j = 0; j < 4; j++)
                    pb[p][j] = W[(size_t)(k0 + bk4 + 16*p + j)*N + col0 + bn];
        }

        MMA_CHUNK(aB0, aB1, bB0, bB1, acc);
        __syncthreads();
    }

#pragma unroll
    for (int mt = 0; mt < 2; mt++)
#pragma unroll
        for (int nt = 0; nt < 4; nt++) {
            int col = col0 + wn + nt*8 + cq*2;
            float b0 = bias[col], b1 = bias[col + 1];
#pragma unroll
            for (int hrow = 0; hrow < 2; hrow++) {
                int row = row0 + wm + mt*16 + r + hrow*8;
                float v0 = acc[mt][nt][hrow*2 + 0] + b0;
                float v1 = acc[mt][nt][hrow*2 + 1] + b1;
                if (act) {
                    v0 = (v0 > 0.f) ? v0 : 0.2f*v0;
                    v1 = (v1 > 0.f) ? v1 : 0.2f*v1;
                }
                *(float2*)&C[(size_t)row*N + col] = make_float2(v0, v1);
            }
        }
}

/* =================== TF32 QK^T (scaled) ================================== */
__global__ void __launch_bounds__(256) qk_tc(
    const float* __restrict__ Q, const float* __restrict__ Km,
    float* __restrict__ Sc)
{
    __shared__ __align__(16) float As[BM][LDA];
    __shared__ __align__(16) float Ks[BN][LDBN];

    const int bh = blockIdx.z;
    const int b = bh >> 4, h = bh & 15;
    const float* Aq = Q  + (size_t)b*SEQ*HID + h*DK;
    const float* Bk = Km + (size_t)b*SEQ*HID + h*DK;
    float* Cp = Sc + (size_t)bh*SEQ*SEQ;
    const int i0 = blockIdx.x * BM;
    const int j0 = blockIdx.y * BN;

    const int tid = threadIdx.x;
    const int arow = tid >> 3, acol = (tid & 7) << 2;
    const int krow = tid >> 3, kcol = (tid & 7) << 2;

    const int wid = tid >> 5, lane = tid & 31;
    const int wm = (wid >> 1) * 32, wn = (wid & 1) * 32;
    const int r = lane >> 2, cq = lane & 3;

    const uint32_t smA = smem_u32(&As[0][0]);
    const uint32_t smB = smem_u32(&Ks[0][0]);
    const uint32_t aB0 = a_frag_base(smA, wm, 0, lane);
    const uint32_t aB1 = a_frag_base(smA, wm, 1, lane);
    const uint32_t bB0 = b_frag_base(smB, wn, 0, lane);
    const uint32_t bB1 = b_frag_base(smB, wn, 1, lane);

    float acc[2][4][4];
#pragma unroll
    for (int mt = 0; mt < 2; mt++)
#pragma unroll
        for (int nt = 0; nt < 4; nt++)
#pragma unroll
            for (int i = 0; i < 4; i++) acc[mt][nt][i] = 0.f;

    float4 pa[4], pk[2];
#pragma unroll
    for (int p = 0; p < 4; p++)
        pa[p] = *(const float4*)(Aq + (size_t)(i0 + arow + 32*p)*HID + acol);
#pragma unroll
    for (int p = 0; p < 2; p++)
        pk[p] = *(const float4*)(Bk + (size_t)(j0 + krow + 32*p)*HID + kcol);

    for (int c = 0; c < DK/BK; c++) {
#pragma unroll
        for (int p = 0; p < 4; p++)
            *(float4*)&As[arow + 32*p][acol] = cvt4(pa[p]);
#pragma unroll
        for (int p = 0; p < 2; p++)
            *(float4*)&Ks[krow + 32*p][kcol] = cvt4(pk[p]);
        __syncthreads();

        if (c + 1 < DK/BK) {
            int k0 = (c + 1) * BK;
#pragma unroll
            for (int p = 0; p < 4; p++)
                pa[p] = *(const float4*)(Aq + (size_t)(i0 + arow + 32*p)*HID + k0 + acol);
#pragma unroll
            for (int p = 0; p < 2; p++)
                pk[p] = *(const float4*)(Bk + (size_t)(j0 + krow + 32*p)*HID + k0 + kcol);
        }

        MMA_CHUNK(aB0, aB1, bB0, bB1, acc);
        __syncthreads();
    }

#pragma unroll
    for (int mt = 0; mt < 2; mt++)
#pragma unroll
        for (int nt = 0; nt < 4; nt++) {
            int col = j0 + wn + nt*8 + cq*2;
#pragma unroll
            for (int hrow = 0; hrow < 2; hrow++) {
                int row = i0 + wm + mt*16 + r + hrow*8;
                *(float2*)&Cp[(size_t)row*SEQ + col] =
                    make_float2(acc[mt][nt][hrow*2+0] * 0.125f,
                                acc[mt][nt][hrow*2+1] * 0.125f);
            }
        }
}

/* =========== per-row softmax stats: max + 1/sum (mask folded) ============ */
__global__ void __launch_bounds__(256) stats_kernel(
    const float* __restrict__ Sc, const int* __restrict__ mask,
    float* __restrict__ gm, float* __restrict__ ginv)
{
    const int i  = blockIdx.x;
    const int bh = blockIdx.y;
    const int b  = bh >> 4;
    const float* row = Sc + ((size_t)bh*SEQ + i)*SEQ;
    const int* mrow = mask + b*SEQ;
    const int tid = threadIdx.x;

    float loc[8];
    float m = -3.4e38f;
#pragma unroll
    for (int t = 0; t < 8; t++) {
        int j = tid + (t << 8);
        float v = row[j];
        if (mrow[j] == 0) v = -1e20f;
        loc[t] = v;
        m = fmaxf(m, v);
    }

    __shared__ float red[8];
    __shared__ float bcv[2];
#pragma unroll
    for (int o = 16; o; o >>= 1) m = fmaxf(m, __shfl_xor_sync(0xffffffffu, m, o));
    if ((tid & 31) == 0) red[tid >> 5] = m;
    __syncthreads();
    if (tid == 0) {
        float mm = red[0];
        for (int w = 1; w < 8; w++) mm = fmaxf(mm, red[w]);
        bcv[0] = mm;
    }
    __syncthreads();
    m = bcv[0];

    float s = 0.f;
#pragma unroll
    for (int t = 0; t < 8; t++) s += __expf(loc[t] - m);
#pragma unroll
    for (int o = 16; o; o >>= 1) s += __shfl_xor_sync(0xffffffffu, s, o);
    if ((tid & 31) == 0) red[tid >> 5] = s;
    __syncthreads();
    if (tid == 0) {
        float ss = 0.f;
        for (int w = 0; w < 8; w++) ss += red[w];
        bcv[1] = ss;
    }
    __syncthreads();
    if (tid == 0) {
        gm  [(size_t)bh*SEQ + i] = m;
        ginv[(size_t)bh*SEQ + i] = 1.f / bcv[1];
    }
}

/* =================== TF32 PV with fused exp/normalize ==================== */
__global__ void __launch_bounds__(256) pv_tc(
    const float* __restrict__ Sc, const float* __restrict__ V,
    const int* __restrict__ mask,
    const float* __restrict__ gm, const float* __restrict__ ginv,
    float* __restrict__ Cv)
{
    __shared__ __align__(16) float As[BM][LDA];
    __shared__ __align__(16) float Bs[BN][LDBN];
    __shared__ float sm_m[BM], sm_v[BM];

    const int bh = blockIdx.z;
    const int b = bh >> 4, h = bh & 15;
    const float* Ap = Sc + (size_t)bh*SEQ*SEQ;
    const float* Bv = V  + (size_t)b*SEQ*HID + h*DK;
    const int* mrow = mask + b*SEQ;
    float* Cp = Cv + (size_t)b*SEQ*HID + h*DK;
    const int i0 = blockIdx.x * BM;

    const int tid = threadIdx.x;
    const int arow = tid >> 3, acol = (tid & 7) << 2;
    const int bn = tid & 63, bk4 = (tid >> 6) << 2;

    const int wid = tid >> 5, lane = tid & 31;
    const int wm = (wid >> 1) * 32, wn = (wid & 1) * 32;
    const int r = lane >> 2, cq = lane & 3;

    const uint32_t smA = smem_u32(&As[0][0]);
    const uint32_t smB = smem_u32(&Bs[0][0]);
    const uint32_t aB0 = a_frag_base(smA, wm, 0, lane);
    const uint32_t aB1 = a_frag_base(smA, wm, 1, lane);
    const uint32_t bB0 = b_frag_base(smB, wn, 0, lane);
    const uint32_t bB1 = b_frag_base(smB, wn, 1, lane);

    if (tid < BM) {
        sm_m[tid] = gm  [(size_t)bh*SEQ + i0 + tid];
        sm_v[tid] = ginv[(size_t)bh*SEQ + i0 + tid];
    }
    __syncthreads();

    float acc[2][4][4];
#pragma unroll
    for (int mt = 0; mt < 2; mt++)
#pragma unroll
        for (int nt = 0; nt < 4; nt++)
#pragma unroll
            for (int i = 0; i < 4; i++) acc[mt][nt][i] = 0.f;

    float4 pa[4]; float pb[2][4]; int4 pm;
    pm = *(const int4*)(mrow + acol);
#pragma unroll
    for (int p = 0; p < 4; p++)
        pa[p] = *(const float4*)(Ap + (size_t)(i0 + arow + 32*p)*SEQ + acol);
#pragma unroll
    for (int p = 0; p < 2; p++)
#pragma unroll
        for (int j = 0; j < 4; j++)
            pb[p][j] = Bv[(size_t)(bk4 + 16*p + j)*HID + bn];

    const int nch = SEQ / BK;  /* 64 */
    for (int c = 0; c < nch; c++) {
#pragma unroll
        for (int p = 0; p < 4; p++) {
            float mi = sm_m[arow + 32*p];
            float4 s = pa[p];
            float4 pf;
            pf.x = pm.x ? __expf(s.x - mi) : 0.f;
            pf.y = pm.y ? __expf(s.y - mi) : 0.f;
            pf.z = pm.z ? __expf(s.z - mi) : 0.f;
            pf.w = pm.w ? __expf(s.w - mi) : 0.f;
            *(float4*)&As[arow + 32*p][acol] = cvt4(pf);
        }
#pragma unroll
        for (int p = 0; p < 2; p++) {
            float4 t = make_float4(pb[p][0], pb[p][1], pb[p][2], pb[p][3]);
            *(float4*)&Bs[bn][bk4 + 16*p] = cvt4(t);
        }
        __syncthreads();

        if (c + 1 < nch) {
            int k0 = (c + 1) * BK;
            pm = *(const int4*)(mrow + k0 + acol);
#pragma unroll
            for (int p = 0; p < 4; p++)
                pa[p] = *(const float4*)(Ap + (size_t)(i0 + arow + 32*p)*SEQ + k0 + acol);
#pragma unroll
            for (int p = 0; p < 2; p++)
#pragma unroll
                for (int j = 0; j < 4; j++)
                    pb[p][j] = Bv[(size_t)(k0 + bk4 + 16*p + j)*HID + bn];
        }

        MMA_CHUNK(aB0, aB1, bB0, bB1, acc);
        __syncthreads();
    }

#pragma unroll
    for (int mt = 0; mt < 2; mt++)
#pragma unroll
        for (int nt = 0; nt < 4; nt++) {
            int col = wn + nt*8 + cq*2;
#pragma unroll
            for (int hrow = 0; hrow < 2; hrow++) {
                int lrow = wm + mt*16 + r + hrow*8;
                float inv = sm_v[lrow];
                int row = i0 + lrow;
                *(float2*)&Cp[(size_t)row*HID + col] =
                    make_float2(acc[mt][nt][hrow*2+0] * inv,
                                acc[mt][nt][hrow*2+1] * inv);
            }
        }
}

/* ---------------- host orchestration ------------------------------------- */
extern "C" void kernel_launch(void* const* d_in, const int* in_sizes, int n_in,
                              void* d_out, int out_size)
{
    const float* query = (const float*)d_in[0];
    const float* key   = (const float*)d_in[1];
    const float* value = (const float*)d_in[2];
    const int*   mask  = (const int*)  d_in[3];
    const float* Wpq = (const float*)d_in[4],  *bpq = (const float*)d_in[5];
    const float* Wtq = (const float*)d_in[6],  *btq = (const float*)d_in[7];
    const float* Wpk = (const float*)d_in[8],  *bpk = (const float*)d_in[9];
    const float* Wtk = (const float*)d_in[10], *btk = (const float*)d_in[11];
    const float* Wpv = (const float*)d_in[12], *bpv = (const float*)d_in[13];
    const float* Wtv = (const float*)d_in[14], *btv = (const float*)d_in[15];
    const float* Wpo = (const float*)d_in[16], *bpo = (const float*)d_in[17];
    const float* Wto = (const float*)d_in[18], *bto = (const float*)d_in[19];
    float* out = (float*)d_out;

    float *q_, *k_, *v_, *h_, *cv_, *sc_, *m_, *inv_;
    cudaGetSymbolAddress((void**)&q_,   g_q);
    cudaGetSymbolAddress((void**)&k_,   g_k);
    cudaGetSymbolAddress((void**)&v_,   g_v);
    cudaGetSymbolAddress((void**)&h_,   g_h);
    cudaGetSymbolAddress((void**)&cv_,  g_cv);
    cudaGetSymbolAddress((void**)&sc_,  g_sc);
    cudaGetSymbolAddress((void**)&m_,   g_m);
    cudaGetSymbolAddress((void**)&inv_, g_inv);

    dim3 blk(256);
    dim3 gproj(ROWS/BM, FAC/BN);   /* (64, 4)  */
    dim3 gtran(ROWS/BM, HID/BN);   /* (64, 16) */

    linear_tc<<<gproj, blk>>>(query, Wpq, bpq, h_, ROWS, FAC, HID, 1);
    linear_tc<<<gtran, blk>>>(h_,    Wtq, btq, q_, ROWS, HID, FAC, 0);
    linear_tc<<<gproj, blk>>>(key,   Wpk, bpk, h_, ROWS, FAC, HID, 1);
    linear_tc<<<gtran, blk>>>(h_,    Wtk, btk, k_, ROWS, HID, FAC, 0);
    linear_tc<<<gproj, blk>>>(value, Wpv, bpv, h_, ROWS, FAC, HID, 1);
    linear_tc<<<gtran, blk>>>(h_,    Wtv, btv, v_, ROWS, HID, FAC, 0);

    qk_tc<<<dim3(SEQ/BM, SEQ/BN, BH), blk>>>(q_, k_, sc_);
    stats_kernel<<<dim3(SEQ, BH), blk>>>(sc_, mask, m_, inv_);
    pv_tc<<<dim3(SEQ/BM, 1, BH), blk>>>(sc_, v_, mask, m_, inv_, cv_);

    linear_tc<<<gproj, blk>>>(cv_, Wpo, bpo, h_,  ROWS, FAC, HID, 1);
    linear_tc<<<gtran, blk>>>(h_,  Wto, bto, out, ROWS, HID, FAC, 0);
}

// round 6
// speedup vs baseline: 2.9241x; 1.2434x over previous
#include <cuda_runtime.h>
#include <math.h>
#include <stdint.h>

#define NB   4
#define SEQ  2048
#define HID  1024
#define FAC  256
#define NHD  16
#define DK   64
#define ROWS (NB*SEQ)   /* 8192 */
#define BH   (NB*NHD)   /* 64   */

#define BM 128
#define BN 64
#define BK 32
#define LDA  36   /* linear kernels: A smem [BM][LDA] */
#define LDBN 36   /* linear kernels: B smem [BN][LDBN] */

#define KT   64   /* flash: keys per chunk */
#define NCH  (SEQ/KT)
#define LDF  68   /* flash row stride: 272B = 17*16, ldmatrix-legal */

/* ---------------- scratch ------------------------------------------------ */
__device__ float g_q  [ROWS*HID];
__device__ float g_k  [ROWS*HID];
__device__ float g_v  [ROWS*HID];
__device__ float g_h  [ROWS*FAC];
__device__ float g_cv [ROWS*HID];

/* ---------------- helpers ------------------------------------------------ */
__device__ __forceinline__ float tf32r(float x) {
    uint32_t u;
    asm("cvt.rna.tf32.f32 %0, %1;" : "=r"(u) : "f"(x));
    return __uint_as_float(u);
}
__device__ __forceinline__ float4 cvt4(float4 v) {
    v.x = tf32r(v.x); v.y = tf32r(v.y); v.z = tf32r(v.z); v.w = tf32r(v.w);
    return v;
}
__device__ __forceinline__ void mma_tf32(float c[4], const uint32_t a[4], const uint32_t b[2]) {
    asm volatile(
        "mma.sync.aligned.m16n8k8.row.col.f32.tf32.tf32.f32 "
        "{%0,%1,%2,%3}, {%4,%5,%6,%7}, {%8,%9}, {%0,%1,%2,%3};"
        : "+f"(c[0]), "+f"(c[1]), "+f"(c[2]), "+f"(c[3])
        : "r"(a[0]), "r"(a[1]), "r"(a[2]), "r"(a[3]), "r"(b[0]), "r"(b[1]));
}
__device__ __forceinline__ void ldsm4(uint32_t f[4], uint32_t addr) {
    asm volatile("ldmatrix.sync.aligned.m8n8.x4.shared.b16 {%0,%1,%2,%3}, [%4];"
        : "=r"(f[0]), "=r"(f[1]), "=r"(f[2]), "=r"(f[3]) : "r"(addr));
}
__device__ __forceinline__ uint32_t smem_u32(const void* p) {
    return (uint32_t)__cvta_generic_to_shared(p);
}
/* A-side ldmatrix base (m-major smem, stride ld floats): 16x8 fragment */
__device__ __forceinline__ uint32_t frag_base_m(uint32_t base, int row0, int lane, int ld) {
    int lr = lane & 7, sel = lane >> 3;
    int row = row0 + lr + ((sel & 1) << 3);
    int col = (sel & 2) << 1;
    return base + (uint32_t)(row*ld + col)*4u;
}
/* B-side ldmatrix base (n-major smem): covers 2 n-subtiles (n0, n0+8), k 0..7 */
__device__ __forceinline__ uint32_t frag_base_n(uint32_t base, int n0, int lane, int ld) {
    int lr = lane & 7, sel = lane >> 3;
    int row = n0 + lr + ((sel & 2) << 2);
    int col = (sel & 1) << 2;
    return base + (uint32_t)(row*ld + col)*4u;
}

#define MMA_CHUNK(aB0, aB1, bB0, bB1, acc)                                    \
    _Pragma("unroll")                                                         \
    for (int kk = 0; kk < BK; kk += 8) {                                      \
        uint32_t af0[4], af1[4], bq0[4], bq1[4];                              \
        ldsm4(af0, (aB0) + kk*4);                                             \
        ldsm4(af1, (aB1) + kk*4);                                             \
        ldsm4(bq0, (bB0) + kk*4);                                             \
        ldsm4(bq1, (bB1) + kk*4);                                             \
        mma_tf32(acc[0][0], af0, &bq0[0]);                                    \
        mma_tf32(acc[0][1], af0, &bq0[2]);                                    \
        mma_tf32(acc[0][2], af0, &bq1[0]);                                    \
        mma_tf32(acc[0][3], af0, &bq1[2]);                                    \
        mma_tf32(acc[1][0], af1, &bq0[0]);                                    \
        mma_tf32(acc[1][1], af1, &bq0[2]);                                    \
        mma_tf32(acc[1][2], af1, &bq1[0]);                                    \
        mma_tf32(acc[1][3], af1, &bq1[2]);                                    \
    }

/* =================== TF32 linear: C = act(A[M,K]@W[K,N]+b) =============== */
__global__ void __launch_bounds__(256) linear_tc(
    const float* __restrict__ A, const float* __restrict__ W,
    const float* __restrict__ bias, float* __restrict__ C,
    int M, int N, int K, int act)
{
    __shared__ __align__(16) float As[BM][LDA];
    __shared__ __align__(16) float Bs[BN][LDBN];

    const int tid = threadIdx.x;
    const int row0 = blockIdx.x * BM;
    const int col0 = blockIdx.y * BN;

    const int arow = tid >> 3, acol = (tid & 7) << 2;
    const int bn = tid & 63, bk4 = (tid >> 6) << 2;

    const int wid = tid >> 5, lane = tid & 31;
    const int wm = (wid >> 1) * 32, wn = (wid & 1) * 32;
    const int r = lane >> 2, cq = lane & 3;

    const uint32_t smA = smem_u32(&As[0][0]);
    const uint32_t smB = smem_u32(&Bs[0][0]);
    const uint32_t aB0 = frag_base_m(smA, wm,      lane, LDA);
    const uint32_t aB1 = frag_base_m(smA, wm + 16, lane, LDA);
    const uint32_t bB0 = frag_base_n(smB, wn,      lane, LDBN);
    const uint32_t bB1 = frag_base_n(smB, wn + 16, lane, LDBN);

    float acc[2][4][4];
#pragma unroll
    for (int mt = 0; mt < 2; mt++)
#pragma unroll
        for (int nt = 0; nt < 4; nt++)
#pragma unroll
            for (int i = 0; i < 4; i++) acc[mt][nt][i] = 0.f;

    float4 pa[4];
    float  pb[2][4];
    const int nch = K / BK;

#pragma unroll
    for (int p = 0; p < 4; p++)
        pa[p] = *(const float4*)(A + (size_t)(row0 + arow + 32*p)*K + acol);
#pragma unroll
    for (int p = 0; p < 2; p++)
#pragma unroll
        for (int j = 0; j < 4; j++)
            pb[p][j] = W[(size_t)(bk4 + 16*p + j)*N + col0 + bn];

    for (int c = 0; c < nch; c++) {
#pragma unroll
        for (int p = 0; p < 4; p++)
            *(float4*)&As[arow + 32*p][acol] = cvt4(pa[p]);
#pragma unroll
        for (int p = 0; p < 2; p++) {
            float4 t = make_float4(pb[p][0], pb[p][1], pb[p][2], pb[p][3]);
            *(float4*)&Bs[bn][bk4 + 16*p] = cvt4(t);
        }
        __syncthreads();

        if (c + 1 < nch) {
            int k0 = (c + 1) * BK;
#pragma unroll
            for (int p = 0; p < 4; p++)
                pa[p] = *(const float4*)(A + (size_t)(row0 + arow + 32*p)*K + k0 + acol);
#pragma unroll
            for (int p = 0; p < 2; p++)
#pragma unroll
                for (int j = 0; j < 4; j++)
                    pb[p][j] = W[(size_t)(k0 + bk4 + 16*p + j)*N + col0 + bn];
        }

        MMA_CHUNK(aB0, aB1, bB0, bB1, acc);
        __syncthreads();
    }

#pragma unroll
    for (int mt = 0; mt < 2; mt++)
#pragma unroll
        for (int nt = 0; nt < 4; nt++) {
            int col = col0 + wn + nt*8 + cq*2;
            float b0 = bias[col], b1 = bias[col + 1];
#pragma unroll
            for (int hrow = 0; hrow < 2; hrow++) {
                int row = row0 + wm + mt*16 + r + hrow*8;
                float v0 = acc[mt][nt][hrow*2 + 0] + b0;
                float v1 = acc[mt][nt][hrow*2 + 1] + b1;
                if (act) {
                    v0 = (v0 > 0.f) ? v0 : 0.2f*v0;
                    v1 = (v1 > 0.f) ? v1 : 0.2f*v1;
                }
                *(float2*)&C[(size_t)row*N + col] = make_float2(v0, v1);
            }
        }
}

/* =================== Flash attention ====================================
   Grid: (SEQ/128, BH). 8 warps; warp w owns query rows w*16..w*16+15 and the
   FULL 64-key chunk width + full d=64 output: softmax stats are warp-local. */
#define FLASH_SMEM ((128*LDF + 2*KT*LDF + 2*KT*LDF + 128*LDF + 2*KT) * 4)

__global__ void __launch_bounds__(256) flash_tc(
    const float* __restrict__ Q, const float* __restrict__ K,
    const float* __restrict__ V, const int* __restrict__ mask,
    float* __restrict__ Cv)
{
    extern __shared__ __align__(16) float sm[];
    float* Qs = sm;                       /* 128*LDF */
    float* Ks = Qs + 128*LDF;             /* 2*KT*LDF */
    float* Vs = Ks + 2*KT*LDF;            /* 2*KT*LDF */
    float* Ps = Vs + 2*KT*LDF;            /* 128*LDF */
    float* MB = Ps + 128*LDF;             /* 2*KT    */

    const int bh = blockIdx.y;
    const int b = bh >> 4, h = bh & 15;
    const int i0 = blockIdx.x * 128;
    const float* Qp = Q + (size_t)b*SEQ*HID + h*DK;
    const float* Kp = K + (size_t)b*SEQ*HID + h*DK;
    const float* Vp = V + (size_t)b*SEQ*HID + h*DK;
    const int* mrow = mask + b*SEQ;
    float* Cp = Cv + (size_t)b*SEQ*HID + h*DK;

    const int tid = threadIdx.x;
    const int wid = tid >> 5, lane = tid & 31;
    const int wm = wid * 16;            /* 16 query rows per warp */
    const int r = lane >> 2, cq = lane & 3;

    const int ld_d = (tid & 15) << 2;
    const int ld_k = tid >> 4;

    /* ---- load Q tile (once) ---- */
#pragma unroll
    for (int p = 0; p < 8; p++) {
        int row = ld_k + p*16;
        float4 qv = *(const float4*)(Qp + (size_t)(i0 + row)*HID + ld_d);
        *(float4*)&Qs[row*LDF + ld_d] = cvt4(qv);
    }
    /* ---- load chunk 0 K/V + mask bias ---- */
#pragma unroll
    for (int p = 0; p < 4; p++) {
        int key = ld_k + p*16;
        float4 kv = *(const float4*)(Kp + (size_t)key*HID + ld_d);
        float4 vv = *(const float4*)(Vp + (size_t)key*HID + ld_d);
        *(float4*)&Ks[key*LDF + ld_d] = cvt4(kv);
        *(float4*)&Vs[key*LDF + ld_d] = cvt4(vv);
    }
    if (tid < KT) MB[tid] = mrow[tid] ? 0.f : -1e20f;
    __syncthreads();

    const uint32_t aQ = frag_base_m(smem_u32(Qs), wm, lane, LDF);
    const uint32_t aP = frag_base_m(smem_u32(Ps), wm, lane, LDF);
    uint32_t bKf[2][4];
#pragma unroll
    for (int buf = 0; buf < 2; buf++)
#pragma unroll
        for (int g = 0; g < 4; g++)
            bKf[buf][g] = frag_base_n(smem_u32(Ks + buf*KT*LDF), g*16, lane, LDF);

    float acc_o[8][4];
#pragma unroll
    for (int nt = 0; nt < 8; nt++)
#pragma unroll
        for (int i = 0; i < 4; i++) acc_o[nt][i] = 0.f;
    float m_st[2] = {-1e20f, -1e20f};
    float l_st[2] = {0.f, 0.f};

    for (int c = 0; c < NCH; c++) {
        const int cur = c & 1, nxt = cur ^ 1;

        /* 1. prefetch next K/V into regs */
        float4 pk[4], pv4[4];
        float mb_next = 0.f;
        if (c + 1 < NCH) {
            const size_t koff = (size_t)(c + 1) * KT;
#pragma unroll
            for (int p = 0; p < 4; p++) {
                int key = ld_k + p*16;
                pk[p]  = *(const float4*)(Kp + (koff + key)*HID + ld_d);
                pv4[p] = *(const float4*)(Vp + (koff + key)*HID + ld_d);
            }
            if (tid < KT) mb_next = mrow[koff + tid] ? 0.f : -1e20f;
        }

        /* 2. S = Q @ K^T: warp rows wm..wm+15, all 64 keys */
        float acc_s[8][4];
#pragma unroll
        for (int nt = 0; nt < 8; nt++)
#pragma unroll
            for (int i = 0; i < 4; i++) acc_s[nt][i] = 0.f;
#pragma unroll
        for (int kk = 0; kk < DK; kk += 8) {
            uint32_t af[4];
            ldsm4(af, aQ + kk*4);
#pragma unroll
            for (int g = 0; g < 4; g++) {
                uint32_t bq[4];
                ldsm4(bq, bKf[cur][g] + kk*4);
                mma_tf32(acc_s[2*g    ], af, &bq[0]);
                mma_tf32(acc_s[2*g + 1], af, &bq[2]);
            }
        }

        /* 3. stage next K/V + mask into other buffer */
        if (c + 1 < NCH) {
            float* Kn = Ks + nxt*KT*LDF;
            float* Vn = Vs + nxt*KT*LDF;
#pragma unroll
            for (int p = 0; p < 4; p++) {
                int key = ld_k + p*16;
                *(float4*)&Kn[key*LDF + ld_d] = cvt4(pk[p]);
                *(float4*)&Vn[key*LDF + ld_d] = cvt4(pv4[p]);
            }
            if (tid < KT) MB[nxt*KT + tid] = mb_next;
        }

        /* 4. online softmax (warp-local: full 64-key row per warp) */
        const float* mb = MB + cur*KT;
        float bias2[8][2];
#pragma unroll
        for (int nt = 0; nt < 8; nt++) {
            bias2[nt][0] = mb[nt*8 + cq*2];
            bias2[nt][1] = mb[nt*8 + cq*2 + 1];
        }
        float alpha[2];
#pragma unroll
        for (int rr = 0; rr < 2; rr++) {
            float mx = -3.4e38f;
#pragma unroll
            for (int nt = 0; nt < 8; nt++)
#pragma unroll
                for (int cc = 0; cc < 2; cc++) {
                    float s = acc_s[nt][rr*2+cc] * 0.125f + bias2[nt][cc];
                    acc_s[nt][rr*2+cc] = s;
                    mx = fmaxf(mx, s);
                }
            mx = fmaxf(mx, __shfl_xor_sync(0xffffffffu, mx, 1));
            mx = fmaxf(mx, __shfl_xor_sync(0xffffffffu, mx, 2));
            float m_new = fmaxf(m_st[rr], mx);
            float a = __expf(m_st[rr] - m_new);
            m_st[rr] = m_new;
            alpha[rr] = a;
            float lsum = 0.f;
#pragma unroll
            for (int nt = 0; nt < 8; nt++)
#pragma unroll
                for (int cc = 0; cc < 2; cc++) {
                    float p = __expf(acc_s[nt][rr*2+cc] - m_new);
                    acc_s[nt][rr*2+cc] = p;
                    lsum += p;
                }
            l_st[rr] = l_st[rr]*a + lsum;
        }
#pragma unroll
        for (int nt = 0; nt < 8; nt++)
#pragma unroll
            for (int i = 0; i < 4; i++) acc_o[nt][i] *= alpha[i>>1];

        /* 5. write P (warp-private region of Ps) */
#pragma unroll
        for (int rr = 0; rr < 2; rr++) {
            int prow = wm + rr*8 + r;
#pragma unroll
            for (int nt = 0; nt < 8; nt++)
                *(float2*)&Ps[prow*LDF + nt*8 + cq*2] =
                    make_float2(tf32r(acc_s[nt][rr*2+0]), tf32r(acc_s[nt][rr*2+1]));
        }
        __syncwarp();

        /* 6. O += P @ V (A: ldmatrix from own Ps rows; B: scalar LDS, k-major V) */
        {
            const float* Vsc = Vs + cur*KT*LDF;
#pragma unroll
            for (int kk = 0; kk < KT; kk += 8) {
                uint32_t af[4];
                ldsm4(af, aP + kk*4);
#pragma unroll
                for (int nt = 0; nt < 8; nt++) {
                    uint32_t bv[2];
                    bv[0] = __float_as_uint(Vsc[(kk + cq    )*LDF + nt*8 + r]);
                    bv[1] = __float_as_uint(Vsc[(kk + cq + 4)*LDF + nt*8 + r]);
                    mma_tf32(acc_o[nt], af, bv);
                }
            }
        }
        __syncthreads();  /* Vs[cur]/MB[cur] free; Ks[nxt] published */
    }

    /* epilogue: normalize rows, write out */
    float inv2[2];
#pragma unroll
    for (int rr = 0; rr < 2; rr++) {
        float lt = l_st[rr];
        lt += __shfl_xor_sync(0xffffffffu, lt, 1);
        lt += __shfl_xor_sync(0xffffffffu, lt, 2);
        inv2[rr] = 1.f / lt;
    }
#pragma unroll
    for (int nt = 0; nt < 8; nt++) {
        int col = nt*8 + cq*2;
#pragma unroll
        for (int rr = 0; rr < 2; rr++) {
            int row = i0 + wm + rr*8 + r;
            *(float2*)&Cp[(size_t)row*HID + col] =
                make_float2(acc_o[nt][rr*2+0]*inv2[rr],
                            acc_o[nt][rr*2+1]*inv2[rr]);
        }
    }
}

/* ---------------- host orchestration ------------------------------------- */
extern "C" void kernel_launch(void* const* d_in, const int* in_sizes, int n_in,
                              void* d_out, int out_size)
{
    const float* query = (const float*)d_in[0];
    const float* key   = (const float*)d_in[1];
    const float* value = (const float*)d_in[2];
    const int*   mask  = (const int*)  d_in[3];
    const float* Wpq = (const float*)d_in[4],  *bpq = (const float*)d_in[5];
    const float* Wtq = (const float*)d_in[6],  *btq = (const float*)d_in[7];
    const float* Wpk = (const float*)d_in[8],  *bpk = (const float*)d_in[9];
    const float* Wtk = (const float*)d_in[10], *btk = (const float*)d_in[11];
    const float* Wpv = (const float*)d_in[12], *bpv = (const float*)d_in[13];
    const float* Wtv = (const float*)d_in[14], *btv = (const float*)d_in[15];
    const float* Wpo = (const float*)d_in[16], *bpo = (const float*)d_in[17];
    const float* Wto = (const float*)d_in[18], *bto = (const float*)d_in[19];
    float* out = (float*)d_out;

    float *q_, *k_, *v_, *h_, *cv_;
    cudaGetSymbolAddress((void**)&q_,  g_q);
    cudaGetSymbolAddress((void**)&k_,  g_k);
    cudaGetSymbolAddress((void**)&v_,  g_v);
    cudaGetSymbolAddress((void**)&h_,  g_h);
    cudaGetSymbolAddress((void**)&cv_, g_cv);

    cudaFuncSetAttribute(flash_tc, cudaFuncAttributeMaxDynamicSharedMemorySize,
                         FLASH_SMEM);

    dim3 blk(256);
    dim3 gproj(ROWS/BM, FAC/BN);   /* (64, 4)  */
    dim3 gtran(ROWS/BM, HID/BN);   /* (64, 16) */

    linear_tc<<<gproj, blk>>>(query, Wpq, bpq, h_, ROWS, FAC, HID, 1);
    linear_tc<<<gtran, blk>>>(h_,    Wtq, btq, q_, ROWS, HID, FAC, 0);
    linear_tc<<<gproj, blk>>>(key,   Wpk, bpk, h_, ROWS, FAC, HID, 1);
    linear_tc<<<gtran, blk>>>(h_,    Wtk, btk, k_, ROWS, HID, FAC, 0);
    linear_tc<<<gproj, blk>>>(value, Wpv, bpv, h_, ROWS, FAC, HID, 1);
    linear_tc<<<gtran, blk>>>(h_,    Wtv, btv, v_, ROWS, HID, FAC, 0);

    flash_tc<<<dim3(SEQ/128, BH), blk, FLASH_SMEM>>>(q_, k_, v_, mask, cv_);

    linear_tc<<<gproj, blk>>>(cv_, Wpo, bpo, h_,  ROWS, FAC, HID, 1);
    linear_tc<<<gtran, blk>>>(h_,  Wto, bto, out, ROWS, HID, FAC, 0);
}

// round 7
// speedup vs baseline: 3.6999x; 1.2653x over previous
#include <cuda_runtime.h>
#include <math.h>
#include <stdint.h>

#define NB   4
#define SEQ  2048
#define HID  1024
#define FAC  256
#define NHD  16
#define DK   64
#define ROWS (NB*SEQ)   /* 8192 */
#define BH   (NB*NHD)   /* 64   */

#define BM 128
#define BN 64
#define BK 32
#define LDA  36   /* linear kernels: A smem [BM][LDA] */
#define LDBN 36   /* linear kernels: B smem [BN][LDBN] */

/* flash geometry */
#define KT   32          /* keys per chunk */
#define NCH  (SEQ/KT)    /* 64 */
#define LDQ  68
#define LDK  68
#define LDV  36
#define LDP  36
#define OFF_Q   0
#define OFF_K   (128*LDQ)                 /* 8704  */
#define OFF_V   (OFF_K + 2*KT*LDK)        /* 13056 */
#define OFF_P   (OFF_V + 2*DK*LDV)        /* 17664 */
#define OFF_MB  (OFF_P + 128*LDP)         /* 22272 */
#define FLASH_FLOATS (OFF_MB + 2*KT)      /* 22336 */
#define FLASH_SMEM   (FLASH_FLOATS*4)     /* 89344 B */

/* ---------------- scratch ------------------------------------------------ */
__device__ float g_q  [ROWS*HID];
__device__ float g_k  [ROWS*HID];
__device__ float g_vt [BH*DK*SEQ];   /* V transposed: [bh][d][token] */
__device__ float g_h  [ROWS*FAC];
__device__ float g_cv [ROWS*HID];

/* ---------------- helpers ------------------------------------------------ */
__device__ __forceinline__ float tf32r(float x) {
    uint32_t u;
    asm("cvt.rna.tf32.f32 %0, %1;" : "=r"(u) : "f"(x));
    return __uint_as_float(u);
}
__device__ __forceinline__ float4 cvt4(float4 v) {
    v.x = tf32r(v.x); v.y = tf32r(v.y); v.z = tf32r(v.z); v.w = tf32r(v.w);
    return v;
}
__device__ __forceinline__ void mma_tf32(float c[4], const uint32_t a[4], const uint32_t b[2]) {
    asm volatile(
        "mma.sync.aligned.m16n8k8.row.col.f32.tf32.tf32.f32 "
        "{%0,%1,%2,%3}, {%4,%5,%6,%7}, {%8,%9}, {%0,%1,%2,%3};"
        : "+f"(c[0]), "+f"(c[1]), "+f"(c[2]), "+f"(c[3])
        : "r"(a[0]), "r"(a[1]), "r"(a[2]), "r"(a[3]), "r"(b[0]), "r"(b[1]));
}
__device__ __forceinline__ void ldsm4(uint32_t f[4], uint32_t addr) {
    asm volatile("ldmatrix.sync.aligned.m8n8.x4.shared.b16 {%0,%1,%2,%3}, [%4];"
        : "=r"(f[0]), "=r"(f[1]), "=r"(f[2]), "=r"(f[3]) : "r"(addr));
}
__device__ __forceinline__ uint32_t smem_u32(const void* p) {
    return (uint32_t)__cvta_generic_to_shared(p);
}
__device__ __forceinline__ void cpa16(uint32_t dst, const void* src) {
    asm volatile("cp.async.cg.shared.global [%0], [%1], 16;" :: "r"(dst), "l"(src));
}
#define CPA_COMMIT() asm volatile("cp.async.commit_group;" ::: "memory")
#define CPA_WAIT0()  asm volatile("cp.async.wait_group 0;" ::: "memory")

/* A-side ldmatrix base (m-major smem): 16x8 fragment */
__device__ __forceinline__ uint32_t frag_base_m(uint32_t base, int row0, int lane, int ld) {
    int lr = lane & 7, sel = lane >> 3;
    int row = row0 + lr + ((sel & 1) << 3);
    int col = (sel & 2) << 1;
    return base + (uint32_t)(row*ld + col)*4u;
}
/* B-side ldmatrix base (n-major smem): 2 n-subtiles (n0, n0+8), k 0..7 */
__device__ __forceinline__ uint32_t frag_base_n(uint32_t base, int n0, int lane, int ld) {
    int lr = lane & 7, sel = lane >> 3;
    int row = n0 + lr + ((sel & 2) << 2);
    int col = (sel & 1) << 2;
    return base + (uint32_t)(row*ld + col)*4u;
}

#define MMA_CHUNK(aB0, aB1, bB0, bB1, acc)                                    \
    _Pragma("unroll")                                                         \
    for (int kk = 0; kk < BK; kk += 8) {                                      \
        uint32_t af0[4], af1[4], bq0[4], bq1[4];                              \
        ldsm4(af0, (aB0) + kk*4);                                             \
        ldsm4(af1, (aB1) + kk*4);                                             \
        ldsm4(bq0, (bB0) + kk*4);                                             \
        ldsm4(bq1, (bB1) + kk*4);                                             \
        mma_tf32(acc[0][0], af0, &bq0[0]);                                    \
        mma_tf32(acc[0][1], af0, &bq0[2]);                                    \
        mma_tf32(acc[0][2], af0, &bq1[0]);                                    \
        mma_tf32(acc[0][3], af0, &bq1[2]);                                    \
        mma_tf32(acc[1][0], af1, &bq0[0]);                                    \
        mma_tf32(acc[1][1], af1, &bq0[2]);                                    \
        mma_tf32(acc[1][2], af1, &bq1[0]);                                    \
        mma_tf32(acc[1][3], af1, &bq1[2]);                                    \
    }

/* =================== TF32 linear =========================================
   act: 0 = bias; 1 = bias+leaky(0.2); 2 = bias+tf32 round;
        3 = bias+tf32 round + TRANSPOSED store into Vt[bh][d][token]       */
__global__ void __launch_bounds__(256) linear_tc(
    const float* __restrict__ A, const float* __restrict__ W,
    const float* __restrict__ bias, float* __restrict__ C,
    int M, int N, int K, int act)
{
    __shared__ __align__(16) float As[BM][LDA];
    __shared__ __align__(16) float Bs[BN][LDBN];

    const int tid = threadIdx.x;
    const int row0 = blockIdx.x * BM;
    const int col0 = blockIdx.y * BN;

    const int arow = tid >> 3, acol = (tid & 7) << 2;
    const int bn = tid & 63, bk4 = (tid >> 6) << 2;

    const int wid = tid >> 5, lane = tid & 31;
    const int wm = (wid >> 1) * 32, wn = (wid & 1) * 32;
    const int r = lane >> 2, cq = lane & 3;

    const uint32_t smA = smem_u32(&As[0][0]);
    const uint32_t smB = smem_u32(&Bs[0][0]);
    const uint32_t aB0 = frag_base_m(smA, wm,      lane, LDA);
    const uint32_t aB1 = frag_base_m(smA, wm + 16, lane, LDA);
    const uint32_t bB0 = frag_base_n(smB, wn,      lane, LDBN);
    const uint32_t bB1 = frag_base_n(smB, wn + 16, lane, LDBN);

    float acc[2][4][4];
#pragma unroll
    for (int mt = 0; mt < 2; mt++)
#pragma unroll
        for (int nt = 0; nt < 4; nt++)
#pragma unroll
            for (int i = 0; i < 4; i++) acc[mt][nt][i] = 0.f;

    float4 pa[4];
    float  pb[2][4];
    const int nch = K / BK;

#pragma unroll
    for (int p = 0; p < 4; p++)
        pa[p] = *(const float4*)(A + (size_t)(row0 + arow + 32*p)*K + acol);
#pragma unroll
    for (int p = 0; p < 2; p++)
#pragma unroll
        for (int j = 0; j < 4; j++)
            pb[p][j] = W[(size_t)(bk4 + 16*p + j)*N + col0 + bn];

    for (int c = 0; c < nch; c++) {
#pragma unroll
        for (int p = 0; p < 4; p++)
            *(float4*)&As[arow + 32*p][acol] = cvt4(pa[p]);
#pragma unroll
        for (int p = 0; p < 2; p++) {
            float4 t = make_float4(pb[p][0], pb[p][1], pb[p][2], pb[p][3]);
            *(float4*)&Bs[bn][bk4 + 16*p] = cvt4(t);
        }
        __syncthreads();

        if (c + 1 < nch) {
            int k0 = (c + 1) * BK;
#pragma unroll
            for (int p = 0; p < 4; p++)
                pa[p] = *(const float4*)(A + (size_t)(row0 + arow + 32*p)*K + k0 + acol);
#pragma unroll
            for (int p = 0; p < 2; p++)
#pragma unroll
                for (int j = 0; j < 4; j++)
                    pb[p][j] = W[(size_t)(k0 + bk4 + 16*p + j)*N + col0 + bn];
        }

        MMA_CHUNK(aB0, aB1, bB0, bB1, acc);
        __syncthreads();
    }

#pragma unroll
    for (int mt = 0; mt < 2; mt++)
#pragma unroll
        for (int nt = 0; nt < 4; nt++) {
            int col = col0 + wn + nt*8 + cq*2;
            float b0 = bias[col], b1 = bias[col + 1];
#pragma unroll
            for (int hrow = 0; hrow < 2; hrow++) {
                int row = row0 + wm + mt*16 + r + hrow*8;
                float v0 = acc[mt][nt][hrow*2 + 0] + b0;
                float v1 = acc[mt][nt][hrow*2 + 1] + b1;
                if (act == 1) {
                    v0 = (v0 > 0.f) ? v0 : 0.2f*v0;
                    v1 = (v1 > 0.f) ? v1 : 0.2f*v1;
                } else if (act >= 2) {
                    v0 = tf32r(v0); v1 = tf32r(v1);
                }
                if (act == 3) {
                    int bb = row >> 11, token = row & (SEQ - 1);
                    int h0 = col >> 6, d0 = col & 63;   /* d0 even -> d0+1 same head */
                    float* dst = C + ((size_t)(bb*NHD + h0)*DK + d0)*SEQ + token;
                    dst[0]   = v0;
                    dst[SEQ] = v1;
                } else {
                    *(float2*)&C[(size_t)row*N + col] = make_float2(v0, v1);
                }
            }
        }
}

/* =================== Flash attention v2 ==================================
   Grid (SEQ/128, BH), 256 thr, 2 CTAs/SM. Warp owns 16 q-rows, full chunk
   width and full d: softmax stats warp-local. KT=32 double-buffered K/Vt
   via cp.async; V pre-transposed so PV B-operand is ldmatrix-clean.       */
__global__ void __launch_bounds__(256, 2) flash_tc(
    const float* __restrict__ Q, const float* __restrict__ K,
    const float* __restrict__ Vt, const int* __restrict__ mask,
    float* __restrict__ Cv)
{
    extern __shared__ __align__(16) float sm[];
    const uint32_t smBase = smem_u32(sm);
    const uint32_t smQ = smBase + OFF_Q*4u;
    const uint32_t smK[2] = { smBase + OFF_K*4u, smBase + (OFF_K + KT*LDK)*4u };
    const uint32_t smV[2] = { smBase + OFF_V*4u, smBase + (OFF_V + DK*LDV)*4u };
    const uint32_t smP = smBase + OFF_P*4u;
    const uint32_t smM = smBase + OFF_MB*4u;
    const int* MBI = (const int*)(sm + OFF_MB);

    const int bh = blockIdx.y;
    const int b = bh >> 4, h = bh & 15;
    const int i0 = blockIdx.x * 128;
    const float* Qp  = Q  + (size_t)b*SEQ*HID + h*DK;
    const float* Kp  = K  + (size_t)b*SEQ*HID + h*DK;
    const float* Vtp = Vt + (size_t)bh*DK*SEQ;
    const int* mrow = mask + b*SEQ;
    float* Cp = Cv + (size_t)b*SEQ*HID + h*DK;

    const int tid = threadIdx.x;
    const int wid = tid >> 5, lane = tid & 31;
    const int wm = wid * 16;
    const int r = lane >> 2, cq = lane & 3;

    /* ---- prologue: async-load Q tile + chunk 0 ---- */
#pragma unroll
    for (int p = 0; p < 8; p++) {
        int idx = p*256 + tid;
        int row = idx >> 4, u = idx & 15;
        cpa16(smQ + (uint32_t)(row*LDQ + u*4)*4u,
              Qp + (size_t)(i0 + row)*HID + u*4);
    }
#pragma unroll
    for (int p = 0; p < 2; p++) {
        int idx = p*256 + tid;
        int krow = idx >> 4, ku = idx & 15;
        cpa16(smK[0] + (uint32_t)(krow*LDK + ku*4)*4u,
              Kp + (size_t)krow*HID + ku*4);
        int vrow = idx >> 3, vu = idx & 7;
        cpa16(smV[0] + (uint32_t)(vrow*LDV + vu*4)*4u,
              Vtp + (size_t)vrow*SEQ + vu*4);
    }
    if (tid < 8) cpa16(smM + (uint32_t)(tid*4)*4u, mrow + tid*4);
    CPA_COMMIT();

    const uint32_t aQ = frag_base_m(smQ, wm, lane, LDQ);
    const uint32_t aP = frag_base_m(smP, wm, lane, LDP);
    uint32_t bKf[2][2], bVf[2][4];
#pragma unroll
    for (int buf = 0; buf < 2; buf++) {
#pragma unroll
        for (int g = 0; g < 2; g++) bKf[buf][g] = frag_base_n(smK[buf], g*16, lane, LDK);
#pragma unroll
        for (int g = 0; g < 4; g++) bVf[buf][g] = frag_base_n(smV[buf], g*16, lane, LDV);
    }

    float acc_o[8][4];
#pragma unroll
    for (int nt = 0; nt < 8; nt++)
#pragma unroll
        for (int i = 0; i < 4; i++) acc_o[nt][i] = 0.f;
    float m_st[2] = {-1e20f, -1e20f};
    float l_st[2] = {0.f, 0.f};

    for (int c = 0; c < NCH; c++) {
        const int cur = c & 1, nxt = cur ^ 1;

        CPA_WAIT0();
        __syncthreads();   /* chunk c visible; all warps done with buffer nxt */

        if (c + 1 < NCH) {
            const size_t k0 = (size_t)(c + 1) * KT;
#pragma unroll
            for (int p = 0; p < 2; p++) {
                int idx = p*256 + tid;
                int krow = idx >> 4, ku = idx & 15;
                cpa16(smK[nxt] + (uint32_t)(krow*LDK + ku*4)*4u,
                      Kp + (k0 + krow)*HID + ku*4);
                int vrow = idx >> 3, vu = idx & 7;
                cpa16(smV[nxt] + (uint32_t)(vrow*LDV + vu*4)*4u,
                      Vtp + (size_t)vrow*SEQ + k0 + vu*4);
            }
            if (tid < 8) cpa16(smM + (uint32_t)(nxt*KT + tid*4)*4u, mrow + k0 + tid*4);
            CPA_COMMIT();
        }

        /* S = Q @ K^T : 16 rows x 32 keys per warp */
        float acc_s[4][4];
#pragma unroll
        for (int nt = 0; nt < 4; nt++)
#pragma unroll
            for (int i = 0; i < 4; i++) acc_s[nt][i] = 0.f;
#pragma unroll
        for (int kk = 0; kk < DK; kk += 8) {
            uint32_t af[4];
            ldsm4(af, aQ + kk*4);
#pragma unroll
            for (int g = 0; g < 2; g++) {
                uint32_t bq[4];
                ldsm4(bq, bKf[cur][g] + kk*4);
                mma_tf32(acc_s[2*g    ], af, &bq[0]);
                mma_tf32(acc_s[2*g + 1], af, &bq[2]);
            }
        }

        /* online softmax (warp-local rows) */
        const int* mi = MBI + cur*KT;
        float bias2[4][2];
#pragma unroll
        for (int nt = 0; nt < 4; nt++) {
            int j = nt*8 + cq*2;
            bias2[nt][0] = mi[j]     ? 0.f : -1e20f;
            bias2[nt][1] = mi[j + 1] ? 0.f : -1e20f;
        }
        float alpha[2];
#pragma unroll
        for (int rr = 0; rr < 2; rr++) {
            float mx = -3.4e38f;
#pragma unroll
            for (int nt = 0; nt < 4; nt++)
#pragma unroll
                for (int cc = 0; cc < 2; cc++) {
                    float s = acc_s[nt][rr*2+cc] * 0.125f + bias2[nt][cc];
                    acc_s[nt][rr*2+cc] = s;
                    mx = fmaxf(mx, s);
                }
            mx = fmaxf(mx, __shfl_xor_sync(0xffffffffu, mx, 1));
            mx = fmaxf(mx, __shfl_xor_sync(0xffffffffu, mx, 2));
            float m_new = fmaxf(m_st[rr], mx);
            float a = __expf(m_st[rr] - m_new);
            m_st[rr] = m_new;
            alpha[rr] = a;
            float lsum = 0.f;
#pragma unroll
            for (int nt = 0; nt < 4; nt++)
#pragma unroll
                for (int cc = 0; cc < 2; cc++) {
                    float p = __expf(acc_s[nt][rr*2+cc] - m_new);
                    acc_s[nt][rr*2+cc] = p;
                    lsum += p;
                }
            l_st[rr] = l_st[rr]*a + lsum;
        }
#pragma unroll
        for (int nt = 0; nt < 8; nt++)
#pragma unroll
            for (int i = 0; i < 4; i++) acc_o[nt][i] *= alpha[i>>1];

        /* write P (warp-private rows of Ps) */
#pragma unroll
        for (int rr = 0; rr < 2; rr++) {
            int prow = wm + rr*8 + r;
#pragma unroll
            for (int nt = 0; nt < 4; nt++)
                *(float2*)&sm[OFF_P + prow*LDP + nt*8 + cq*2] =
                    make_float2(tf32r(acc_s[nt][rr*2+0]), tf32r(acc_s[nt][rr*2+1]));
        }
        __syncwarp();

        /* O += P @ V : B from transposed V via ldmatrix */
#pragma unroll
        for (int kk = 0; kk < KT; kk += 8) {
            uint32_t af[4];
            ldsm4(af, aP + kk*4);
#pragma unroll
            for (int g = 0; g < 4; g++) {
                uint32_t bv[4];
                ldsm4(bv, bVf[cur][g] + kk*4);
                mma_tf32(acc_o[2*g    ], af, &bv[0]);
                mma_tf32(acc_o[2*g + 1], af, &bv[2]);
            }
        }
        /* no trailing barrier: next iter's top sync protects buffer reuse */
    }

    /* epilogue */
    float inv2[2];
#pragma unroll
    for (int rr = 0; rr < 2; rr++) {
        float lt = l_st[rr];
        lt += __shfl_xor_sync(0xffffffffu, lt, 1);
        lt += __shfl_xor_sync(0xffffffffu, lt, 2);
        inv2[rr] = 1.f / lt;
    }
#pragma unroll
    for (int nt = 0; nt < 8; nt++) {
        int col = nt*8 + cq*2;
#pragma unroll
        for (int rr = 0; rr < 2; rr++) {
            int row = i0 + wm + rr*8 + r;
            *(float2*)&Cp[(size_t)row*HID + col] =
                make_float2(acc_o[nt][rr*2+0]*inv2[rr],
                            acc_o[nt][rr*2+1]*inv2[rr]);
        }
    }
}

/* ---------------- host orchestration ------------------------------------- */
extern "C" void kernel_launch(void* const* d_in, const int* in_sizes, int n_in,
                              void* d_out, int out_size)
{
    const float* query = (const float*)d_in[0];
    const float* key   = (const float*)d_in[1];
    const float* value = (const float*)d_in[2];
    const int*   mask  = (const int*)  d_in[3];
    const float* Wpq = (const float*)d_in[4],  *bpq = (const float*)d_in[5];
    const float* Wtq = (const float*)d_in[6],  *btq = (const float*)d_in[7];
    const float* Wpk = (const float*)d_in[8],  *bpk = (const float*)d_in[9];
    const float* Wtk = (const float*)d_in[10], *btk = (const float*)d_in[11];
    const float* Wpv = (const float*)d_in[12], *bpv = (const float*)d_in[13];
    const float* Wtv = (const float*)d_in[14], *btv = (const float*)d_in[15];
    const float* Wpo = (const float*)d_in[16], *bpo = (const float*)d_in[17];
    const float* Wto = (const float*)d_in[18], *bto = (const float*)d_in[19];
    float* out = (float*)d_out;

    float *q_, *k_, *vt_, *h_, *cv_;
    cudaGetSymbolAddress((void**)&q_,  g_q);
    cudaGetSymbolAddress((void**)&k_,  g_k);
    cudaGetSymbolAddress((void**)&vt_, g_vt);
    cudaGetSymbolAddress((void**)&h_,  g_h);
    cudaGetSymbolAddress((void**)&cv_, g_cv);

    cudaFuncSetAttribute(flash_tc, cudaFuncAttributeMaxDynamicSharedMemorySize,
                         FLASH_SMEM);

    dim3 blk(256);
    dim3 gproj(ROWS/BM, FAC/BN);   /* (64, 4)  */
    dim3 gtran(ROWS/BM, HID/BN);   /* (64, 16) */

    linear_tc<<<gproj, blk>>>(query, Wpq, bpq, h_, ROWS, FAC, HID, 1);
    linear_tc<<<gtran, blk>>>(h_,    Wtq, btq, q_, ROWS, HID, FAC, 2);
    linear_tc<<<gproj, blk>>>(key,   Wpk, bpk, h_, ROWS, FAC, HID, 1);
    linear_tc<<<gtran, blk>>>(h_,    Wtk, btk, k_, ROWS, HID, FAC, 2);
    linear_tc<<<gproj, blk>>>(value, Wpv, bpv, h_, ROWS, FAC, HID, 1);
    linear_tc<<<gtran, blk>>>(h_,    Wtv, btv, vt_, ROWS, HID, FAC, 3);

    flash_tc<<<dim3(SEQ/128, BH), blk, FLASH_SMEM>>>(q_, k_, vt_, mask, cv_);

    linear_tc<<<gproj, blk>>>(cv_, Wpo, bpo, h_,  ROWS, FAC, HID, 1);
    linear_tc<<<gtran, blk>>>(h_,  Wto, bto, out, ROWS, HID, FAC, 0);
}